// round 1
// baseline (speedup 1.0000x reference)
#include <cuda_runtime.h>
#include <cuda_bf16.h>

// Problem constants (fixed by the dataset)
#define NN 50000     // nodes
#define RR 16        // relations
#define DD 200       // hidden dim
#define EE 400000    // edges

#define TILE_E 32            // edges per CTA tile in the relation GEMM
#define GEMM_THREADS 200     // 25 col-threads x 8 edge-groups
#define MAX_TILES (EE / TILE_E + RR)   // 12516 upper bound on total tiles

// ---------------- device scratch (static; no runtime allocation) ------------
__device__ int   g_cnt[RR * NN];       // per (relation,dst) edge count
__device__ float g_invc[RR * NN];      // 1 / max(cnt,1)
__device__ int   g_hist[RR];           // edges per relation
__device__ int   g_off[RR + 1];        // prefix offsets into sorted edge arrays
__device__ int   g_cursor[RR];         // scatter cursors
__device__ int   g_src[EE];            // edges sorted by relation
__device__ int   g_dst[EE];
__device__ int   g_ntiles;
__device__ int   g_tile_rel[MAX_TILES];
__device__ int   g_tile_start[MAX_TILES];
__device__ float g_h[NN * DD];         // layer-1 hidden state (40 MB)

// ---------------- small kernels ---------------------------------------------
__global__ void k_init() {
    int i = blockIdx.x * blockDim.x + threadIdx.x;
    if (i < RR * NN) g_cnt[i] = 0;
    if (i < RR) { g_hist[i] = 0; g_cursor[i] = 0; }
    if (i == RR) g_ntiles = 0;
}

__global__ void k_hist(const int* __restrict__ etype, const int* __restrict__ dst) {
    __shared__ int sh[RR];
    if (threadIdx.x < RR) sh[threadIdx.x] = 0;
    __syncthreads();
    int i = blockIdx.x * blockDim.x + threadIdx.x;
    if (i < EE) {
        int r = etype[i];
        atomicAdd(&sh[r], 1);
        atomicAdd(&g_cnt[r * NN + dst[i]], 1);
    }
    __syncthreads();
    if (threadIdx.x < RR) atomicAdd(&g_hist[threadIdx.x], sh[threadIdx.x]);
}

__global__ void k_invc() {
    int i = blockIdx.x * blockDim.x + threadIdx.x;
    if (i < RR * NN) g_invc[i] = 1.0f / fmaxf((float)g_cnt[i], 1.0f);
}

__global__ void k_offsets() {
    __shared__ int tb[RR + 1];
    if (threadIdx.x == 0) {
        int o = 0;
        for (int r = 0; r < RR; r++) { g_off[r] = o; o += g_hist[r]; }
        g_off[RR] = o;
        int t = 0;
        for (int r = 0; r < RR; r++) { tb[r] = t; t += (g_hist[r] + TILE_E - 1) / TILE_E; }
        tb[RR] = t;
        g_ntiles = t;
    }
    __syncthreads();
    int nt = tb[RR];
    for (int i = threadIdx.x; i < nt; i += blockDim.x) {
        int r = 0;
        while (!(i >= tb[r] && i < tb[r + 1])) r++;
        g_tile_rel[i] = r;
        g_tile_start[i] = g_off[r] + (i - tb[r]) * TILE_E;
    }
}

__global__ void k_sort(const int* __restrict__ src, const int* __restrict__ dst,
                       const int* __restrict__ etype) {
    int i = blockIdx.x * blockDim.x + threadIdx.x;
    if (i >= EE) return;
    int r = etype[i];
    unsigned act = __activemask();
    unsigned mask = __match_any_sync(act, r);
    int lane = threadIdx.x & 31;
    int leader = __ffs(mask) - 1;
    int rank = __popc(mask & ((1u << lane) - 1u));
    int base = 0;
    if (lane == leader) base = atomicAdd(&g_cursor[r], __popc(mask));
    base = __shfl_sync(mask, base, leader);
    int pos = g_off[r] + base + rank;
    g_src[pos] = src[i];
    g_dst[pos] = dst[i];
}

__global__ void k_relu(float* __restrict__ h) {
    int i = blockIdx.x * blockDim.x + threadIdx.x;
    if (i < NN * DD) h[i] = fmaxf(h[i], 0.0f);
}

// ---------------- root GEMM: out = X @ root + b -----------------------------
// CTA: 32 rows x 200 cols, 200 threads; per thread 4 rows x 8 cols.
__global__ __launch_bounds__(GEMM_THREADS)
void k_rootgemm(const float* __restrict__ X, const float* __restrict__ Wm,
                const float* __restrict__ bias, float* __restrict__ out) {
    __shared__ float xs[TILE_E][DD];
    __shared__ float ws[8][DD];
    int tid = threadIdx.x;
    int row0 = blockIdx.x * TILE_E;

    for (int e = 0; e < TILE_E; e++) {
        int rr = min(row0 + e, NN - 1);
        xs[e][tid] = X[rr * DD + tid];
    }

    int tx = tid % 25;          // column phase: cols tx + 25*j
    int ty = tid / 25;          // edge group: rows 4*ty .. 4*ty+3
    float acc[4][8];
    #pragma unroll
    for (int i = 0; i < 4; i++)
        #pragma unroll
        for (int j = 0; j < 8; j++) acc[i][j] = 0.0f;

    for (int k0 = 0; k0 < DD; k0 += 8) {
        __syncthreads();
        #pragma unroll
        for (int i = tid; i < 8 * DD; i += GEMM_THREADS)
            ws[i / DD][i % DD] = Wm[(k0 + i / DD) * DD + (i % DD)];
        __syncthreads();
        #pragma unroll
        for (int k = 0; k < 8; k++) {
            float wv[8];
            #pragma unroll
            for (int j = 0; j < 8; j++) wv[j] = ws[k][tx + 25 * j];
            #pragma unroll
            for (int i = 0; i < 4; i++) {
                float xv = xs[4 * ty + i][k0 + k];
                #pragma unroll
                for (int j = 0; j < 8; j++) acc[i][j] += xv * wv[j];
            }
        }
    }

    float bv[8];
    #pragma unroll
    for (int j = 0; j < 8; j++) bv[j] = bias[tx + 25 * j];
    #pragma unroll
    for (int i = 0; i < 4; i++) {
        int row = row0 + 4 * ty + i;
        if (row < NN) {
            #pragma unroll
            for (int j = 0; j < 8; j++)
                out[row * DD + tx + 25 * j] = acc[i][j] + bv[j];
        }
    }
}

// ------- per-relation gather-GEMM-scatter: out[dst] += (x[src]@W[r]) * inv ---
__global__ __launch_bounds__(GEMM_THREADS)
void k_relscatter(const float* __restrict__ X, const float* __restrict__ Wbase,
                  float* __restrict__ out) {
    int b = blockIdx.x;
    if (b >= g_ntiles) return;
    int r = g_tile_rel[b];
    int start = g_tile_start[b];
    int end = g_off[r + 1];
    int cnt = min(TILE_E, end - start);
    const float* Wm = Wbase + r * DD * DD;

    __shared__ float xs[TILE_E][DD];
    __shared__ float ws[8][DD];
    __shared__ int   sdst[TILE_E];
    __shared__ float sinv[TILE_E];

    int tid = threadIdx.x;
    for (int e = 0; e < TILE_E; e++) {
        int s = g_src[start + min(e, cnt - 1)];
        xs[e][tid] = X[s * DD + tid];
    }
    if (tid < TILE_E) {
        if (tid < cnt) {
            int d = g_dst[start + tid];
            sdst[tid] = d;
            sinv[tid] = g_invc[r * NN + d];
        } else {
            sdst[tid] = 0;
            sinv[tid] = 0.0f;
        }
    }

    int tx = tid % 25;
    int ty = tid / 25;
    float acc[4][8];
    #pragma unroll
    for (int i = 0; i < 4; i++)
        #pragma unroll
        for (int j = 0; j < 8; j++) acc[i][j] = 0.0f;

    for (int k0 = 0; k0 < DD; k0 += 8) {
        __syncthreads();
        #pragma unroll
        for (int i = tid; i < 8 * DD; i += GEMM_THREADS)
            ws[i / DD][i % DD] = Wm[(k0 + i / DD) * DD + (i % DD)];
        __syncthreads();
        #pragma unroll
        for (int k = 0; k < 8; k++) {
            float wv[8];
            #pragma unroll
            for (int j = 0; j < 8; j++) wv[j] = ws[k][tx + 25 * j];
            #pragma unroll
            for (int i = 0; i < 4; i++) {
                float xv = xs[4 * ty + i][k0 + k];
                #pragma unroll
                for (int j = 0; j < 8; j++) acc[i][j] += xv * wv[j];
            }
        }
    }

    #pragma unroll
    for (int i = 0; i < 4; i++) {
        int e = 4 * ty + i;
        if (e < cnt) {
            int   drow = sdst[e];
            float inv  = sinv[e];
            #pragma unroll
            for (int j = 0; j < 8; j++)
                atomicAdd(&out[drow * DD + tx + 25 * j], acc[i][j] * inv);
        }
    }
}

// ---------------- launch ------------------------------------------------------
extern "C" void kernel_launch(void* const* d_in, const int* in_sizes, int n_in,
                              void* d_out, int out_size) {
    const int*   edge_index = (const int*)d_in[0];   // [2, E]
    const int*   etype      = (const int*)d_in[1];   // [E]
    const float* emb        = (const float*)d_in[2]; // [N, D]
    const float* W1         = (const float*)d_in[3]; // [R, D, D]
    const float* root1      = (const float*)d_in[4]; // [D, D]
    const float* b1         = (const float*)d_in[5]; // [D]
    const float* W2         = (const float*)d_in[6];
    const float* root2      = (const float*)d_in[7];
    const float* b2         = (const float*)d_in[8];
    float* out = (float*)d_out;

    const int* src = edge_index;
    const int* dst = edge_index + EE;

    int gridRN   = (RR * NN + 255) / 256;
    int gridE    = (EE + 255) / 256;
    int gridRows = (NN + TILE_E - 1) / TILE_E;
    int gridH    = (NN * DD + 255) / 256;

    // Build per-call edge structures (deterministic up to fp atomic order).
    k_init<<<gridRN, 256>>>();
    k_hist<<<gridE, 256>>>(etype, dst);
    k_invc<<<gridRN, 256>>>();
    k_offsets<<<1, 256>>>();
    k_sort<<<gridE, 256>>>(src, dst, etype);

    // Layer 1: h = emb@root1 + b1 ; h += scatter(mean messages) ; relu
    k_rootgemm<<<gridRows, GEMM_THREADS>>>(emb, root1, b1, g_h);
    k_relscatter<<<MAX_TILES, GEMM_THREADS>>>(emb, W1, g_h);
    k_relu<<<gridH, 256>>>(g_h);

    // Layer 2: out = h@root2 + b2 ; out += scatter(mean messages)
    k_rootgemm<<<gridRows, GEMM_THREADS>>>(g_h, root2, b2, out);
    k_relscatter<<<MAX_TILES, GEMM_THREADS>>>(g_h, W2, out);
}

// round 2
// speedup vs baseline: 1.2780x; 1.2780x over previous
#include <cuda_runtime.h>
#include <cuda_bf16.h>

// Problem constants
#define NN 50000
#define RR 16
#define DD 200
#define EE 400000
#define NB (RR * NN)            // 800000 buckets
#define S_MAX EE                // nonzero buckets <= E
#define TM 48                   // GEMM tile rows
#define MAX_TILES (EE / TM + RR)
#define NBLK ((NB + 2047) / 2048)   // scan blocks (2048 elems each)

// ---------------- device scratch ----------------
__device__ int   g_cnt[NB];
__device__ int   g_slotid[NB];
__device__ int   g_srow[S_MAX];      // slot -> dst node
__device__ float g_sinv[S_MAX];      // slot -> 1/cnt
__device__ int   g_eslot[EE];        // edge -> slot
__device__ int   g_bsum[NBLK];
__device__ int   g_bpre[NBLK];
__device__ int   g_roff[RR + 1];     // slot offsets per relation
__device__ int   g_S;
__device__ int   g_ntiles;
__device__ int   g_tile_rel[MAX_TILES];
__device__ int   g_tile_slot[MAX_TILES];
__device__ float g_agg[(long long)S_MAX * DD]; // 320 MB
__device__ float g_h[NN * DD];                 // 40 MB

// ---------------- preprocessing ----------------
__global__ void k_zero_cnt() {
    int i = blockIdx.x * blockDim.x + threadIdx.x;
    if (i < NB) g_cnt[i] = 0;
}

__global__ void k_hist(const int* __restrict__ etype, const int* __restrict__ dst) {
    int i = blockIdx.x * blockDim.x + threadIdx.x;
    if (i < EE) atomicAdd(&g_cnt[etype[i] * NN + dst[i]], 1);
}

__global__ void k_scan1() {
    __shared__ int wsum[8];
    int b = blockIdx.x, tid = threadIdx.x;
    int i0 = b * 2048 + tid * 8;
    int tsum = 0;
    #pragma unroll
    for (int j = 0; j < 8; j++) {
        int i = i0 + j;
        tsum += (i < NB && g_cnt[i] > 0) ? 1 : 0;
    }
    int lane = tid & 31, wid = tid >> 5;
    int v = tsum;
    #pragma unroll
    for (int o = 1; o < 32; o <<= 1) {
        int u = __shfl_up_sync(0xffffffffu, v, o);
        if (lane >= o) v += u;
    }
    if (lane == 31) wsum[wid] = v;
    __syncthreads();
    if (tid == 0) {
        int s = 0;
        #pragma unroll
        for (int w = 0; w < 8; w++) s += wsum[w];
        g_bsum[b] = s;
    }
}

__global__ void k_scan2() {
    __shared__ int sh[512];
    int tid = threadIdx.x;
    int v = (tid < NBLK) ? g_bsum[tid] : 0;
    sh[tid] = v;
    __syncthreads();
    for (int off = 1; off < 512; off <<= 1) {
        int u = (tid >= off) ? sh[tid - off] : 0;
        __syncthreads();
        sh[tid] += u;
        __syncthreads();
    }
    if (tid < NBLK) g_bpre[tid] = sh[tid] - v;   // exclusive
    if (tid == 511) { g_S = sh[511]; g_roff[RR] = sh[511]; }
}

__global__ void k_scan3() {
    __shared__ int wsum[8];
    int b = blockIdx.x, tid = threadIdx.x;
    int i0 = b * 2048 + tid * 8;
    int flags[8];
    int tsum = 0;
    #pragma unroll
    for (int j = 0; j < 8; j++) {
        int i = i0 + j;
        int f = (i < NB && g_cnt[i] > 0) ? 1 : 0;
        flags[j] = f;
        tsum += f;
    }
    int lane = tid & 31, wid = tid >> 5;
    int v = tsum;
    #pragma unroll
    for (int o = 1; o < 32; o <<= 1) {
        int u = __shfl_up_sync(0xffffffffu, v, o);
        if (lane >= o) v += u;
    }
    int texcl = v - tsum;
    if (lane == 31) wsum[wid] = v;
    __syncthreads();
    if (tid == 0) {
        int s = 0;
        #pragma unroll
        for (int w = 0; w < 8; w++) { int t = wsum[w]; wsum[w] = s; s += t; }
    }
    __syncthreads();
    int run = g_bpre[b] + wsum[wid] + texcl;
    #pragma unroll
    for (int j = 0; j < 8; j++) {
        int i = i0 + j;
        if (i < NB) {
            if (i % NN == 0) g_roff[i / NN] = run;
            if (flags[j]) {
                g_slotid[i] = run;
                g_srow[run] = i % NN;
                g_sinv[run] = 1.0f / (float)g_cnt[i];
                run++;
            }
        }
    }
}

__global__ void k_tiles() {
    __shared__ int tb[RR + 1];
    if (threadIdx.x == 0) {
        int t = 0;
        for (int r = 0; r < RR; r++) {
            tb[r] = t;
            int m = g_roff[r + 1] - g_roff[r];
            t += (m + TM - 1) / TM;
        }
        tb[RR] = t;
        g_ntiles = t;
    }
    __syncthreads();
    int nt = tb[RR];
    for (int i = threadIdx.x; i < nt; i += blockDim.x) {
        int r = 0;
        while (i >= tb[r + 1]) r++;
        g_tile_rel[i] = r;
        g_tile_slot[i] = g_roff[r] + (i - tb[r]) * TM;
    }
}

__global__ void k_eslot(const int* __restrict__ etype, const int* __restrict__ dst) {
    int i = blockIdx.x * blockDim.x + threadIdx.x;
    if (i < EE) g_eslot[i] = g_slotid[etype[i] * NN + dst[i]];
}

// ---------------- aggregation ----------------
__global__ void k_zero_agg() {
    int n4 = g_S * 50;
    float4 z = make_float4(0.f, 0.f, 0.f, 0.f);
    for (int i = blockIdx.x * blockDim.x + threadIdx.x; i < n4; i += gridDim.x * blockDim.x)
        ((float4*)g_agg)[i] = z;
}

__global__ void k_agg(const float* __restrict__ x, const int* __restrict__ src) {
    int idx = blockIdx.x * blockDim.x + threadIdx.x;
    if (idx >= EE * 50) return;
    int e = idx / 50, c = idx % 50;
    int s = src[e];
    int slot = g_eslot[e];
    float4 v = ((const float4*)x)[s * 50 + c];
    float* p = g_agg + (long long)slot * DD + c * 4;
    asm volatile("red.global.add.v4.f32 [%0], {%1,%2,%3,%4};"
                 :: "l"(p), "f"(v.x), "f"(v.y), "f"(v.z), "f"(v.w) : "memory");
}

__global__ void k_relu(float* __restrict__ h) {
    int i = blockIdx.x * blockDim.x + threadIdx.x;
    if (i < NN * DD) h[i] = fmaxf(h[i], 0.0f);
}

// ---------------- GEMMs (FFMA2, 48x200 tile, 200 threads) ----------------
#define XS_STRIDE 202

// out[g] = X[g] @ Wm + bias    (dense rows)
__global__ __launch_bounds__(200)
void k_rootgemm(const float* __restrict__ X, const float* __restrict__ Wm,
                const float* __restrict__ bias, float* __restrict__ out) {
    __shared__ float xs[TM * XS_STRIDE];
    __shared__ float ws[8 * DD];
    int tid = threadIdx.x;
    int n0 = blockIdx.x * TM;

    const float2* X2 = (const float2*)X;
    #pragma unroll
    for (int s = 0; s < (TM * 100) / 200; s++) {
        int q = tid + 200 * s;
        int row = q / 100, c2 = q % 100;
        int grow = n0 + row; if (grow >= NN) grow = NN - 1;
        float2 v = X2[grow * 100 + c2];
        *(float2*)&xs[row * XS_STRIDE + 2 * c2] = v;
    }

    int tx = tid % 25, ty = tid / 25;
    unsigned long long acc[6][4];
    #pragma unroll
    for (int i = 0; i < 6; i++)
        #pragma unroll
        for (int j = 0; j < 4; j++) acc[i][j] = 0ull;

    for (int k0 = 0; k0 < DD; k0 += 8) {
        __syncthreads();
        #pragma unroll
        for (int s = 0; s < 2; s++) {
            int q = tid + 200 * s;
            ((float4*)ws)[q] = ((const float4*)(Wm + k0 * DD))[q];
        }
        __syncthreads();
        #pragma unroll
        for (int k = 0; k < 8; k++) {
            unsigned long long xp[6];
            #pragma unroll
            for (int i = 0; i < 6; i++) {
                unsigned int bbits = __float_as_uint(xs[(ty + 8 * i) * XS_STRIDE + k0 + k]);
                asm("mov.b64 %0, {%1, %2};" : "=l"(xp[i]) : "r"(bbits), "r"(bbits));
            }
            #pragma unroll
            for (int j = 0; j < 4; j++) {
                unsigned long long wp = *(const unsigned long long*)&ws[k * DD + 2 * (tx + 25 * j)];
                #pragma unroll
                for (int i = 0; i < 6; i++)
                    asm("fma.rn.f32x2 %0, %1, %2, %0;" : "+l"(acc[i][j]) : "l"(xp[i]), "l"(wp));
            }
        }
    }

    #pragma unroll
    for (int i = 0; i < 6; i++) {
        int g = n0 + ty + 8 * i;
        if (g < NN) {
            #pragma unroll
            for (int j = 0; j < 4; j++) {
                int c = 2 * (tx + 25 * j);
                unsigned int u0, u1;
                asm("mov.b64 {%0, %1}, %2;" : "=r"(u0), "=r"(u1) : "l"(acc[i][j]));
                float2 bv = *(const float2*)&bias[c];
                float2 o;
                o.x = __uint_as_float(u0) + bv.x;
                o.y = __uint_as_float(u1) + bv.y;
                *(float2*)&out[g * DD + c] = o;
            }
        }
    }
}

// out[srow[slot]] += sinv[slot] * (Agg[slot] @ W[rel])   (red.v2 scatter)
__global__ __launch_bounds__(200)
void k_relgemm(const float* __restrict__ Wbase, float* __restrict__ out) {
    int t = blockIdx.x;
    if (t >= g_ntiles) return;
    int r = g_tile_rel[t];
    int s0 = g_tile_slot[t];
    int mrows = g_roff[r + 1] - s0; if (mrows > TM) mrows = TM;
    const float* Wm = Wbase + r * DD * DD;

    __shared__ float xs[TM * XS_STRIDE];
    __shared__ float ws[8 * DD];
    int tid = threadIdx.x;

    const float2* A2 = (const float2*)(g_agg + (long long)s0 * DD);
    #pragma unroll
    for (int s = 0; s < (TM * 100) / 200; s++) {
        int q = tid + 200 * s;
        int row = q / 100, c2 = q % 100;
        float2 v = (row < mrows) ? A2[q] : make_float2(0.f, 0.f);
        *(float2*)&xs[row * XS_STRIDE + 2 * c2] = v;
    }

    int tx = tid % 25, ty = tid / 25;
    unsigned long long acc[6][4];
    #pragma unroll
    for (int i = 0; i < 6; i++)
        #pragma unroll
        for (int j = 0; j < 4; j++) acc[i][j] = 0ull;

    for (int k0 = 0; k0 < DD; k0 += 8) {
        __syncthreads();
        #pragma unroll
        for (int s = 0; s < 2; s++) {
            int q = tid + 200 * s;
            ((float4*)ws)[q] = ((const float4*)(Wm + k0 * DD))[q];
        }
        __syncthreads();
        #pragma unroll
        for (int k = 0; k < 8; k++) {
            unsigned long long xp[6];
            #pragma unroll
            for (int i = 0; i < 6; i++) {
                unsigned int bbits = __float_as_uint(xs[(ty + 8 * i) * XS_STRIDE + k0 + k]);
                asm("mov.b64 %0, {%1, %2};" : "=l"(xp[i]) : "r"(bbits), "r"(bbits));
            }
            #pragma unroll
            for (int j = 0; j < 4; j++) {
                unsigned long long wp = *(const unsigned long long*)&ws[k * DD + 2 * (tx + 25 * j)];
                #pragma unroll
                for (int i = 0; i < 6; i++)
                    asm("fma.rn.f32x2 %0, %1, %2, %0;" : "+l"(acc[i][j]) : "l"(xp[i]), "l"(wp));
            }
        }
    }

    #pragma unroll
    for (int i = 0; i < 6; i++) {
        int row = ty + 8 * i;
        if (row < mrows) {
            int slot = s0 + row;
            float inv = g_sinv[slot];
            long long drow = g_srow[slot];
            #pragma unroll
            for (int j = 0; j < 4; j++) {
                unsigned int u0, u1;
                asm("mov.b64 {%0, %1}, %2;" : "=r"(u0), "=r"(u1) : "l"(acc[i][j]));
                float a0 = __uint_as_float(u0) * inv;
                float a1 = __uint_as_float(u1) * inv;
                float* p = out + drow * DD + 2 * (tx + 25 * j);
                asm volatile("red.global.add.v2.f32 [%0], {%1, %2};"
                             :: "l"(p), "f"(a0), "f"(a1) : "memory");
            }
        }
    }
}

// ---------------- launch ----------------
extern "C" void kernel_launch(void* const* d_in, const int* in_sizes, int n_in,
                              void* d_out, int out_size) {
    const int*   edge_index = (const int*)d_in[0];
    const int*   etype      = (const int*)d_in[1];
    const float* emb        = (const float*)d_in[2];
    const float* W1         = (const float*)d_in[3];
    const float* root1      = (const float*)d_in[4];
    const float* b1         = (const float*)d_in[5];
    const float* W2         = (const float*)d_in[6];
    const float* root2      = (const float*)d_in[7];
    const float* b2         = (const float*)d_in[8];
    float* out = (float*)d_out;

    const int* src = edge_index;
    const int* dst = edge_index + EE;

    int gridNB   = (NB + 255) / 256;
    int gridE    = (EE + 255) / 256;
    int gridAgg  = (EE * 50 + 255) / 256;
    int gridRoot = (NN + TM - 1) / TM;
    int gridH    = (NN * DD + 255) / 256;

    // preprocessing: bucket counts, compaction scan, tile map, edge->slot
    k_zero_cnt<<<gridNB, 256>>>();
    k_hist<<<gridE, 256>>>(etype, dst);
    k_scan1<<<NBLK, 256>>>();
    k_scan2<<<1, 512>>>();
    k_scan3<<<NBLK, 256>>>();
    k_tiles<<<1, 256>>>();
    k_eslot<<<gridE, 256>>>(etype, dst);

    // layer 1
    k_zero_agg<<<8192, 256>>>();
    k_agg<<<gridAgg, 256>>>(emb, src);
    k_rootgemm<<<gridRoot, 200>>>(emb, root1, b1, g_h);
    k_relgemm<<<MAX_TILES, 200>>>(W1, g_h);
    k_relu<<<gridH, 256>>>(g_h);

    // layer 2
    k_zero_agg<<<8192, 256>>>();
    k_agg<<<gridAgg, 256>>>(g_h, src);
    k_rootgemm<<<gridRoot, 200>>>(g_h, root2, b2, out);
    k_relgemm<<<MAX_TILES, 200>>>(W2, out);
}